// round 1
// baseline (speedup 1.0000x reference)
#include <cuda_runtime.h>
#include <math.h>

#define D 128
#define GAMMA 0.1f
#define EPS 0.1f
#define MAXN 100000
#define MAXE 1600000
#define SCAN_BS 1024
#define MAXB ((MAXN + SCAN_BS - 1) / SCAN_BS)

// ---------------- scratch (static device globals; no allocation) ----------------
__device__ __align__(16) float g_xa[MAXN * D];       // x @ A^T
__device__ __align__(16) float g_xw[MAXN * D];       // x @ W_phi^T
__device__ __align__(16) float g_xbuf[MAXN * D];     // ping-pong x buffer
__device__ __align__(16) float g_wcatT[D * 256];     // [k][j]: j<128 -> A, j>=128 -> W_phi
__device__ int   g_deg[MAXN];
__device__ float g_dinv[MAXN];
__device__ int   g_rowptr[MAXN + 1];
__device__ int   g_wptr[MAXN];
__device__ int   g_col[MAXE];
__device__ float g_enorm[MAXE];
__device__ int   g_bsums[MAXB + 2];
__device__ int   g_boff[MAXB + 2];

// ---------------- prep: build concatenated transposed weight ----------------
// g_wcatT[k*256 + j]:
//   j <  128 : A[j][k]  = W[j][k] - W[k][j] - (j==k)*GAMMA   (for x @ A^T)
//   j >= 128 : Wphi[j-128][k]                                 (for x @ Wphi^T)
__global__ void prep_weights(const float* __restrict__ W, const float* __restrict__ Wphi) {
    int idx = blockIdx.x * blockDim.x + threadIdx.x;
    if (idx >= D * 256) return;
    int k = idx / 256;
    int j = idx % 256;
    float v;
    if (j < D) {
        v = W[j * D + k] - W[k * D + j];
        if (j == k) v -= GAMMA;
    } else {
        v = Wphi[(j - D) * D + k];
    }
    g_wcatT[k * 256 + j] = v;
}

// ---------------- degree / dinv ----------------
__global__ void zero_deg(int n) {
    int i = blockIdx.x * blockDim.x + threadIdx.x;
    if (i < n) g_deg[i] = 0;
}

__global__ void count_deg(const int* __restrict__ ei, int e) {
    int idx = blockIdx.x * blockDim.x + threadIdx.x;
    if (idx >= e) return;
    int dst = ei[e + idx];   // edge_index[1][idx]
    atomicAdd(&g_deg[dst], 1);
}

__global__ void dinv_kernel(int n) {
    int i = blockIdx.x * blockDim.x + threadIdx.x;
    if (i < n) g_dinv[i] = rsqrtf((float)g_deg[i] + 1.0f);
}

// ---------------- exclusive scan of deg -> rowptr ----------------
__global__ void scan1(int n) {
    __shared__ int sh[SCAN_BS];
    int tx = threadIdx.x;
    int i = blockIdx.x * SCAN_BS + tx;
    int v = (i < n) ? g_deg[i] : 0;
    sh[tx] = v;
    __syncthreads();
    for (int off = 1; off < SCAN_BS; off <<= 1) {
        int t = (tx >= off) ? sh[tx - off] : 0;
        __syncthreads();
        sh[tx] += t;
        __syncthreads();
    }
    int incl = sh[tx];
    if (i < n) g_rowptr[i] = incl - v;   // local exclusive
    if (tx == SCAN_BS - 1) g_bsums[blockIdx.x] = incl;
}

__global__ void scan2(int nb, int e_total, int n) {
    int run = 0;
    for (int b = 0; b < nb; b++) {
        g_boff[b] = run;
        run += g_bsums[b];
    }
    g_rowptr[n] = e_total;
}

__global__ void scan3(int n) {
    int i = blockIdx.x * blockDim.x + threadIdx.x;
    if (i >= n) return;
    int v = g_rowptr[i] + g_boff[i / SCAN_BS];
    g_rowptr[i] = v;
    g_wptr[i] = v;
}

// ---------------- CSR fill (grouped by dst) ----------------
__global__ void fill_csr(const int* __restrict__ ei, int e) {
    int idx = blockIdx.x * blockDim.x + threadIdx.x;
    if (idx >= e) return;
    int src = ei[idx];
    int dst = ei[e + idx];
    int pos = atomicAdd(&g_wptr[dst], 1);
    g_col[pos] = src;
    g_enorm[pos] = g_dinv[src] * g_dinv[dst];
}

// ---------------- fused GEMM: [xa | xw] = x @ WcatT (fp32, packed f32x2) ----------------
// block: 64 rows x 256 cols, threads (32,8); thread: 8 rows x 8 cols (4 f32x2 pairs)
__global__ __launch_bounds__(256) void gemm_kernel(const float* __restrict__ xin, int n) {
    __shared__ __align__(16) float Wsm[16][256];
    __shared__ __align__(16) float Xsm[64][17];

    int lane = threadIdx.x;
    int ty = threadIdx.y;
    int tid = ty * 32 + lane;
    int rowBase = blockIdx.x * 64;

    unsigned long long acc[8][4];
#pragma unroll
    for (int rr = 0; rr < 8; rr++)
#pragma unroll
        for (int m = 0; m < 4; m++) acc[rr][m] = 0ULL;

    for (int k0 = 0; k0 < D; k0 += 16) {
        // load W chunk (16 x 256 floats, contiguous) as float4
        {
            const float4* src = (const float4*)(g_wcatT + k0 * 256);
            float4* dst = (float4*)(&Wsm[0][0]);
#pragma unroll
            for (int q = tid; q < 1024; q += 256) dst[q] = src[q];
        }
        // load X chunk: 64 rows x 16 cols; each thread one float4
        {
            int r = tid >> 2;
            int seg = tid & 3;
            int row = rowBase + r;
            float4 v = make_float4(0.f, 0.f, 0.f, 0.f);
            if (row < n) v = *(const float4*)(xin + row * D + k0 + seg * 4);
            Xsm[r][seg * 4 + 0] = v.x;
            Xsm[r][seg * 4 + 1] = v.y;
            Xsm[r][seg * 4 + 2] = v.z;
            Xsm[r][seg * 4 + 3] = v.w;
        }
        __syncthreads();

#pragma unroll
        for (int kk = 0; kk < 16; kk++) {
            unsigned long long xp[8];
#pragma unroll
            for (int rr = 0; rr < 8; rr++) {
                float xv = Xsm[ty * 8 + rr][kk];
                asm("mov.b64 %0, {%1, %1};" : "=l"(xp[rr]) : "f"(xv));
            }
            unsigned long long wv[4];
#pragma unroll
            for (int m = 0; m < 4; m++) {
                wv[m] = *(const unsigned long long*)(&Wsm[kk][2 * lane + 64 * m]);
            }
#pragma unroll
            for (int rr = 0; rr < 8; rr++) {
#pragma unroll
                for (int m = 0; m < 4; m++) {
                    asm("fma.rn.f32x2 %0, %1, %2, %3;"
                        : "=l"(acc[rr][m])
                        : "l"(xp[rr]), "l"(wv[m]), "l"(acc[rr][m]));
                }
            }
        }
        __syncthreads();
    }

    // epilogue: cols 0..127 -> g_xa, cols 128..255 -> g_xw
#pragma unroll
    for (int rr = 0; rr < 8; rr++) {
        int row = rowBase + ty * 8 + rr;
        if (row >= n) continue;
#pragma unroll
        for (int m = 0; m < 4; m++) {
            float lo, hi;
            asm("mov.b64 {%0, %1}, %2;" : "=f"(lo), "=f"(hi) : "l"(acc[rr][m]));
            int col = 2 * lane + 64 * (m & 1);
            float* base = (m < 2) ? (g_xa + row * D) : (g_xw + row * D);
            *(float2*)(base + col) = make_float2(lo, hi);
        }
    }
}

// ---------------- fused aggregate + update ----------------
// one warp per node; lane owns 4 cols (float4)
__global__ __launch_bounds__(256) void agg_update(const float* __restrict__ xin,
                                                  float* __restrict__ xout,
                                                  const float* __restrict__ bias,
                                                  int n) {
    int gwarp = (blockIdx.x * blockDim.x + threadIdx.x) >> 5;
    int lane = threadIdx.x & 31;
    if (gwarp >= n) return;
    int i = gwarp;

    int start = g_rowptr[i];
    int end = g_rowptr[i + 1];

    const float4* xw4 = (const float4*)g_xw;
    float4 acc = make_float4(0.f, 0.f, 0.f, 0.f);

    for (int j = start; j < end; j += 32) {
        int cnt = min(32, end - j);
        int c = 0;
        float w = 0.f;
        if (lane < cnt) {
            c = g_col[j + lane];
            w = g_enorm[j + lane];
        }
        int t = 0;
        for (; t + 4 <= cnt; t += 4) {
            int c0 = __shfl_sync(0xFFFFFFFFu, c, t + 0);
            int c1 = __shfl_sync(0xFFFFFFFFu, c, t + 1);
            int c2 = __shfl_sync(0xFFFFFFFFu, c, t + 2);
            int c3 = __shfl_sync(0xFFFFFFFFu, c, t + 3);
            float w0 = __shfl_sync(0xFFFFFFFFu, w, t + 0);
            float w1 = __shfl_sync(0xFFFFFFFFu, w, t + 1);
            float w2 = __shfl_sync(0xFFFFFFFFu, w, t + 2);
            float w3 = __shfl_sync(0xFFFFFFFFu, w, t + 3);
            float4 v0 = __ldg(&xw4[c0 * 32 + lane]);
            float4 v1 = __ldg(&xw4[c1 * 32 + lane]);
            float4 v2 = __ldg(&xw4[c2 * 32 + lane]);
            float4 v3 = __ldg(&xw4[c3 * 32 + lane]);
            acc.x += w0 * v0.x; acc.y += w0 * v0.y; acc.z += w0 * v0.z; acc.w += w0 * v0.w;
            acc.x += w1 * v1.x; acc.y += w1 * v1.y; acc.z += w1 * v1.z; acc.w += w1 * v1.w;
            acc.x += w2 * v2.x; acc.y += w2 * v2.y; acc.z += w2 * v2.z; acc.w += w2 * v2.w;
            acc.x += w3 * v3.x; acc.y += w3 * v3.y; acc.z += w3 * v3.z; acc.w += w3 * v3.w;
        }
        for (; t < cnt; t++) {
            int cc = __shfl_sync(0xFFFFFFFFu, c, t);
            float ww = __shfl_sync(0xFFFFFFFFu, w, t);
            float4 v = __ldg(&xw4[cc * 32 + lane]);
            acc.x += ww * v.x; acc.y += ww * v.y; acc.z += ww * v.z; acc.w += ww * v.w;
        }
    }

    float dv = g_dinv[i];
    float d2 = dv * dv;

    float4 xa = __ldg(&((const float4*)g_xa)[i * 32 + lane]);
    float4 xwv = __ldg(&xw4[i * 32 + lane]);
    float4 xv = __ldg(&((const float4*)xin)[i * 32 + lane]);
    float4 bv = __ldg(&((const float4*)bias)[lane]);

    float4 pre;
    pre.x = xa.x + acc.x + xwv.x * d2 + bv.x;
    pre.y = xa.y + acc.y + xwv.y * d2 + bv.y;
    pre.z = xa.z + acc.z + xwv.z * d2 + bv.z;
    pre.w = xa.w + acc.w + xwv.w * d2 + bv.w;

    float4 o;
    o.x = xv.x + EPS * tanhf(pre.x);
    o.y = xv.y + EPS * tanhf(pre.y);
    o.z = xv.z + EPS * tanhf(pre.z);
    o.w = xv.w + EPS * tanhf(pre.w);

    ((float4*)xout)[i * 32 + lane] = o;
}

// ---------------- launch ----------------
extern "C" void kernel_launch(void* const* d_in, const int* in_sizes, int n_in,
                              void* d_out, int out_size) {
    const float* x0   = (const float*)d_in[0];
    const int*   ei   = (const int*)d_in[1];
    const float* W    = (const float*)d_in[2];
    const float* Wphi = (const float*)d_in[3];
    const float* bias = (const float*)d_in[4];

    int n = in_sizes[0] / D;
    int e = in_sizes[1] / 2;
    if (n > MAXN) n = MAXN;
    if (e > MAXE) e = MAXE;

    float* xbuf = nullptr;
    cudaGetSymbolAddress((void**)&xbuf, g_xbuf);
    float* outp = (float*)d_out;

    // one-time graph preprocessing
    prep_weights<<<(D * 256 + 255) / 256, 256>>>(W, Wphi);
    zero_deg<<<(n + 255) / 256, 256>>>(n);
    count_deg<<<(e + 255) / 256, 256>>>(ei, e);
    dinv_kernel<<<(n + 255) / 256, 256>>>(n);
    int nb = (n + SCAN_BS - 1) / SCAN_BS;
    scan1<<<nb, SCAN_BS>>>(n);
    scan2<<<1, 1>>>(nb, e, n);
    scan3<<<(n + 255) / 256, 256>>>(n);
    fill_csr<<<(e + 255) / 256, 256>>>(ei, e);

    // 4 iterations, ping-pong: x0 -> xbuf -> d_out -> xbuf -> d_out
    const float* xin = x0;
    for (int it = 0; it < 4; it++) {
        float* xout = (it % 2 == 0) ? xbuf : outp;
        gemm_kernel<<<(n + 63) / 64, dim3(32, 8)>>>(xin, n);
        agg_update<<<(n + 7) / 8, 256>>>(xin, xout, bias, n);
        xin = xout;
    }
}

// round 3
// speedup vs baseline: 1.6566x; 1.6566x over previous
#include <cuda_runtime.h>
#include <math.h>
#include <stdint.h>

#define D 128
#define GAMMA 0.1f
#define EPS 0.1f
#define MAXN 100000
#define MAXE 1600000
#define SCAN_BS 1024
#define MAXB ((MAXN + SCAN_BS - 1) / SCAN_BS)

// ---------------- scratch (static device globals; no allocation) ----------------
__device__ __align__(16) float g_xa[MAXN * D];       // x @ A^T
__device__ __align__(16) float g_xw[MAXN * D];       // x @ W_phi^T
__device__ __align__(16) float g_xbuf[MAXN * D];     // ping-pong x buffer
__device__ __align__(16) float g_wcat[256 * D];      // row j<128: A row j; j>=128: Wphi row j-128
__device__ int   g_deg[MAXN];
__device__ float g_dinv[MAXN];
__device__ int   g_rowptr[MAXN + 1];
__device__ int   g_wptr[MAXN];
__device__ int   g_col[MAXE];
__device__ float g_enorm[MAXE];
__device__ int   g_bsums[MAXB + 2];
__device__ int   g_boff[MAXB + 2];

// ---------------- prep: build concatenated weight (row-major [j][k]) ----------------
__global__ void prep_weights(const float* __restrict__ W, const float* __restrict__ Wphi) {
    int idx = blockIdx.x * blockDim.x + threadIdx.x;
    if (idx >= 256 * D) return;
    int j = idx / D;
    int k = idx % D;
    float v;
    if (j < D) {
        v = W[j * D + k] - W[k * D + j];
        if (j == k) v -= GAMMA;
    } else {
        v = Wphi[(j - D) * D + k];
    }
    g_wcat[j * D + k] = v;
}

// ---------------- degree / dinv ----------------
__global__ void zero_deg(int n) {
    int i = blockIdx.x * blockDim.x + threadIdx.x;
    if (i < n) g_deg[i] = 0;
}
__global__ void count_deg(const int* __restrict__ ei, int e) {
    int idx = blockIdx.x * blockDim.x + threadIdx.x;
    if (idx >= e) return;
    atomicAdd(&g_deg[ei[e + idx]], 1);
}
__global__ void dinv_kernel(int n) {
    int i = blockIdx.x * blockDim.x + threadIdx.x;
    if (i < n) g_dinv[i] = rsqrtf((float)g_deg[i] + 1.0f);
}

// ---------------- exclusive scan of deg -> rowptr ----------------
__global__ void scan1(int n) {
    __shared__ int sh[SCAN_BS];
    int tx = threadIdx.x;
    int i = blockIdx.x * SCAN_BS + tx;
    int v = (i < n) ? g_deg[i] : 0;
    sh[tx] = v;
    __syncthreads();
    for (int off = 1; off < SCAN_BS; off <<= 1) {
        int t = (tx >= off) ? sh[tx - off] : 0;
        __syncthreads();
        sh[tx] += t;
        __syncthreads();
    }
    int incl = sh[tx];
    if (i < n) g_rowptr[i] = incl - v;
    if (tx == SCAN_BS - 1) g_bsums[blockIdx.x] = incl;
}
__global__ void scan2(int nb, int e_total, int n) {
    int run = 0;
    for (int b = 0; b < nb; b++) { g_boff[b] = run; run += g_bsums[b]; }
    g_rowptr[n] = e_total;
}
__global__ void scan3(int n) {
    int i = blockIdx.x * blockDim.x + threadIdx.x;
    if (i >= n) return;
    int v = g_rowptr[i] + g_boff[i / SCAN_BS];
    g_rowptr[i] = v;
    g_wptr[i] = v;
}
__global__ void fill_csr(const int* __restrict__ ei, int e) {
    int idx = blockIdx.x * blockDim.x + threadIdx.x;
    if (idx >= e) return;
    int src = ei[idx];
    int dst = ei[e + idx];
    int pos = atomicAdd(&g_wptr[dst], 1);
    g_col[pos] = src;
    g_enorm[pos] = g_dinv[src] * g_dinv[dst];
}

// ---------------- tf32 mma.sync GEMM: [xa | xw] = x @ wcat^T ----------------
// block: 512 threads (16 warps, 4x4 warp grid), tile 128 rows x 256 cols, K=128
// SMEM: A [128][132] f32(tf32), B [256][132] f32(tf32)  -> 202,752 bytes
#define GT 512
#define LDP 132
#define GEMM_SMEM ((128 * LDP + 256 * LDP) * 4)

__device__ __forceinline__ uint32_t f2tf32(float f) {
    uint32_t u;
    asm("cvt.rna.tf32.f32 %0, %1;" : "=r"(u) : "f"(f));
    return u;
}

__global__ __launch_bounds__(GT, 1) void gemm_mma(const float* __restrict__ xin, int n) {
    extern __shared__ float sm[];
    float* As = sm;               // 128 x 132
    float* Bs = sm + 128 * LDP;   // 256 x 132

    int tid = threadIdx.x;
    int wid = tid >> 5;
    int lane = tid & 31;
    int rowBase = blockIdx.x << 7;

    // load B (weights), tf32-rounded: 256 rows x 128 cols
    for (int i = tid; i < 256 * 32; i += GT) {
        int j = i >> 5, c4 = i & 31;
        float4 v = ((const float4*)g_wcat)[i];
        float* dst = Bs + j * LDP + c4 * 4;
        dst[0] = __uint_as_float(f2tf32(v.x));
        dst[1] = __uint_as_float(f2tf32(v.y));
        dst[2] = __uint_as_float(f2tf32(v.z));
        dst[3] = __uint_as_float(f2tf32(v.w));
    }
    // load A tile (zero-pad OOB rows), tf32-rounded
    for (int i = tid; i < 128 * 32; i += GT) {
        int r = i >> 5, c4 = i & 31;
        int row = rowBase + r;
        float4 v = make_float4(0.f, 0.f, 0.f, 0.f);
        if (row < n) v = *(const float4*)(xin + row * D + c4 * 4);
        float* dst = As + r * LDP + c4 * 4;
        dst[0] = __uint_as_float(f2tf32(v.x));
        dst[1] = __uint_as_float(f2tf32(v.y));
        dst[2] = __uint_as_float(f2tf32(v.z));
        dst[3] = __uint_as_float(f2tf32(v.w));
    }
    __syncthreads();

    int wm = wid >> 2;        // 0..3 : rows 32 each
    int wn = wid & 3;         // 0..3 : cols 64 each
    int grp = lane >> 2;      // groupID 0..7
    int tig = lane & 3;       // thread in group 0..3

    float c[2][8][4];
#pragma unroll
    for (int mt = 0; mt < 2; mt++)
#pragma unroll
        for (int nt = 0; nt < 8; nt++)
#pragma unroll
            for (int q = 0; q < 4; q++) c[mt][nt][q] = 0.f;

    const float* Abase = As + (wm * 32 + grp) * LDP + tig;
    const float* Bbase = Bs + (wn * 64 + grp) * LDP + tig;

#pragma unroll
    for (int ks = 0; ks < 16; ks++) {
        int k0 = ks * 8;
        uint32_t a[2][4], b[8][2];
#pragma unroll
        for (int mt = 0; mt < 2; mt++) {
            const float* ap = Abase + mt * 16 * LDP + k0;
            a[mt][0] = __float_as_uint(ap[0]);
            a[mt][1] = __float_as_uint(ap[8 * LDP]);
            a[mt][2] = __float_as_uint(ap[4]);
            a[mt][3] = __float_as_uint(ap[8 * LDP + 4]);
        }
#pragma unroll
        for (int nt = 0; nt < 8; nt++) {
            const float* bp = Bbase + nt * 8 * LDP + k0;
            b[nt][0] = __float_as_uint(bp[0]);
            b[nt][1] = __float_as_uint(bp[4]);
        }
#pragma unroll
        for (int mt = 0; mt < 2; mt++) {
#pragma unroll
            for (int nt = 0; nt < 8; nt++) {
                asm volatile(
                    "mma.sync.aligned.m16n8k8.row.col.f32.tf32.tf32.f32 "
                    "{%0,%1,%2,%3}, {%4,%5,%6,%7}, {%8,%9}, {%0,%1,%2,%3};"
                    : "+f"(c[mt][nt][0]), "+f"(c[mt][nt][1]),
                      "+f"(c[mt][nt][2]), "+f"(c[mt][nt][3])
                    : "r"(a[mt][0]), "r"(a[mt][1]), "r"(a[mt][2]), "r"(a[mt][3]),
                      "r"(b[nt][0]), "r"(b[nt][1]));
            }
        }
    }

    // epilogue: wn 0,1 -> xa cols 0..127 ; wn 2,3 -> xw cols 0..127
    float* outg = (wn < 2) ? g_xa : g_xw;
    int colBase = (wn & 1) * 64 + 2 * tig;
#pragma unroll
    for (int mt = 0; mt < 2; mt++) {
        int r0 = rowBase + wm * 32 + mt * 16 + grp;
        int r1 = r0 + 8;
#pragma unroll
        for (int nt = 0; nt < 8; nt++) {
            int col = colBase + nt * 8;
            if (r0 < n)
                *(float2*)(outg + r0 * D + col) = make_float2(c[mt][nt][0], c[mt][nt][1]);
            if (r1 < n)
                *(float2*)(outg + r1 * D + col) = make_float2(c[mt][nt][2], c[mt][nt][3]);
        }
    }
}

// ---------------- fused aggregate + update ----------------
__global__ __launch_bounds__(256) void agg_update(const float* __restrict__ xin,
                                                  float* __restrict__ xout,
                                                  const float* __restrict__ bias,
                                                  int n) {
    int gwarp = (blockIdx.x * blockDim.x + threadIdx.x) >> 5;
    int lane = threadIdx.x & 31;
    if (gwarp >= n) return;
    int i = gwarp;

    int start = g_rowptr[i];
    int end = g_rowptr[i + 1];

    const float4* xw4 = (const float4*)g_xw;
    float4 acc = make_float4(0.f, 0.f, 0.f, 0.f);

    for (int j = start; j < end; j += 32) {
        int cnt = min(32, end - j);
        int c = 0;
        float w = 0.f;
        if (lane < cnt) {
            c = g_col[j + lane];
            w = g_enorm[j + lane];
        }
        int t = 0;
        for (; t + 4 <= cnt; t += 4) {
            int c0 = __shfl_sync(0xFFFFFFFFu, c, t + 0);
            int c1 = __shfl_sync(0xFFFFFFFFu, c, t + 1);
            int c2 = __shfl_sync(0xFFFFFFFFu, c, t + 2);
            int c3 = __shfl_sync(0xFFFFFFFFu, c, t + 3);
            float w0 = __shfl_sync(0xFFFFFFFFu, w, t + 0);
            float w1 = __shfl_sync(0xFFFFFFFFu, w, t + 1);
            float w2 = __shfl_sync(0xFFFFFFFFu, w, t + 2);
            float w3 = __shfl_sync(0xFFFFFFFFu, w, t + 3);
            float4 v0 = __ldg(&xw4[c0 * 32 + lane]);
            float4 v1 = __ldg(&xw4[c1 * 32 + lane]);
            float4 v2 = __ldg(&xw4[c2 * 32 + lane]);
            float4 v3 = __ldg(&xw4[c3 * 32 + lane]);
            acc.x += w0 * v0.x; acc.y += w0 * v0.y; acc.z += w0 * v0.z; acc.w += w0 * v0.w;
            acc.x += w1 * v1.x; acc.y += w1 * v1.y; acc.z += w1 * v1.z; acc.w += w1 * v1.w;
            acc.x += w2 * v2.x; acc.y += w2 * v2.y; acc.z += w2 * v2.z; acc.w += w2 * v2.w;
            acc.x += w3 * v3.x; acc.y += w3 * v3.y; acc.z += w3 * v3.z; acc.w += w3 * v3.w;
        }
        for (; t < cnt; t++) {
            int cc = __shfl_sync(0xFFFFFFFFu, c, t);
            float ww = __shfl_sync(0xFFFFFFFFu, w, t);
            float4 v = __ldg(&xw4[cc * 32 + lane]);
            acc.x += ww * v.x; acc.y += ww * v.y; acc.z += ww * v.z; acc.w += ww * v.w;
        }
    }

    float dv = g_dinv[i];
    float d2 = dv * dv;

    float4 xa = __ldg(&((const float4*)g_xa)[i * 32 + lane]);
    float4 xwv = __ldg(&xw4[i * 32 + lane]);
    float4 xv = __ldg(&((const float4*)xin)[i * 32 + lane]);
    float4 bv = __ldg(&((const float4*)bias)[lane]);

    float4 pre;
    pre.x = xa.x + acc.x + xwv.x * d2 + bv.x;
    pre.y = xa.y + acc.y + xwv.y * d2 + bv.y;
    pre.z = xa.z + acc.z + xwv.z * d2 + bv.z;
    pre.w = xa.w + acc.w + xwv.w * d2 + bv.w;

    float4 o;
    o.x = xv.x + EPS * tanhf(pre.x);
    o.y = xv.y + EPS * tanhf(pre.y);
    o.z = xv.z + EPS * tanhf(pre.z);
    o.w = xv.w + EPS * tanhf(pre.w);

    ((float4*)xout)[i * 32 + lane] = o;
}

// ---------------- launch ----------------
extern "C" void kernel_launch(void* const* d_in, const int* in_sizes, int n_in,
                              void* d_out, int out_size) {
    const float* x0   = (const float*)d_in[0];
    const int*   ei   = (const int*)d_in[1];
    const float* W    = (const float*)d_in[2];
    const float* Wphi = (const float*)d_in[3];
    const float* bias = (const float*)d_in[4];

    int n = in_sizes[0] / D;
    int e = in_sizes[1] / 2;
    if (n > MAXN) n = MAXN;
    if (e > MAXE) e = MAXE;

    float* xbuf = nullptr;
    cudaGetSymbolAddress((void**)&xbuf, g_xbuf);
    float* outp = (float*)d_out;

    cudaFuncSetAttribute(gemm_mma, cudaFuncAttributeMaxDynamicSharedMemorySize, GEMM_SMEM);

    // one-time graph preprocessing
    prep_weights<<<(256 * D + 255) / 256, 256>>>(W, Wphi);
    zero_deg<<<(n + 255) / 256, 256>>>(n);
    count_deg<<<(e + 255) / 256, 256>>>(ei, e);
    dinv_kernel<<<(n + 255) / 256, 256>>>(n);
    int nb = (n + SCAN_BS - 1) / SCAN_BS;
    scan1<<<nb, SCAN_BS>>>(n);
    scan2<<<1, 1>>>(nb, e, n);
    scan3<<<(n + 255) / 256, 256>>>(n);
    fill_csr<<<(e + 255) / 256, 256>>>(ei, e);

    // 4 iterations, ping-pong: x0 -> xbuf -> d_out -> xbuf -> d_out
    const float* xin = x0;
    int tiles = (n + 127) >> 7;
    for (int it = 0; it < 4; it++) {
        float* xout = (it % 2 == 0) ? xbuf : outp;
        gemm_mma<<<tiles, GT, GEMM_SMEM>>>(xin, n);
        agg_update<<<(n + 7) / 8, 256>>>(xin, xout, bias, n);
        xin = xout;
    }
}

// round 4
// speedup vs baseline: 1.7971x; 1.0848x over previous
#include <cuda_runtime.h>
#include <cuda_fp16.h>
#include <math.h>
#include <stdint.h>

#define D 128
#define GAMMA 0.1f
#define EPS 0.1f
#define MAXN 100000
#define MAXE 1600000
#define SCAN_BS 1024
#define MAXB ((MAXN + SCAN_BS - 1) / SCAN_BS)

// ---------------- scratch (static device globals; no allocation) ----------------
__device__ __align__(16) float  g_xa[MAXN * D];      // x @ A^T (fp32)
__device__ __align__(16) __half g_xwh[MAXN * D];     // x @ W_phi^T (fp16, for gather)
__device__ __align__(16) float  g_xbuf[MAXN * D];    // ping-pong x buffer
__device__ __align__(16) float  g_wcat[256 * D];     // row j<128: A row j; j>=128: Wphi row j-128
__device__ int   g_deg[MAXN];
__device__ float g_dinv[MAXN];
__device__ int   g_rowptr[MAXN + 1];
__device__ int   g_wptr[MAXN];
__device__ int   g_col[MAXE];
__device__ float g_enorm[MAXE];
__device__ int   g_bsums[MAXB + 2];
__device__ int   g_boff[MAXB + 2];

// ---------------- prep: build concatenated weight (row-major [j][k]) ----------------
__global__ void prep_weights(const float* __restrict__ W, const float* __restrict__ Wphi) {
    int idx = blockIdx.x * blockDim.x + threadIdx.x;
    if (idx >= 256 * D) return;
    int j = idx / D;
    int k = idx % D;
    float v;
    if (j < D) {
        v = W[j * D + k] - W[k * D + j];
        if (j == k) v -= GAMMA;
    } else {
        v = Wphi[(j - D) * D + k];
    }
    g_wcat[j * D + k] = v;
}

// ---------------- degree / dinv ----------------
__global__ void zero_deg(int n) {
    int i = blockIdx.x * blockDim.x + threadIdx.x;
    if (i < n) g_deg[i] = 0;
}
__global__ void count_deg(const int* __restrict__ ei, int e) {
    int idx = blockIdx.x * blockDim.x + threadIdx.x;
    if (idx >= e) return;
    atomicAdd(&g_deg[ei[e + idx]], 1);
}
__global__ void dinv_kernel(int n) {
    int i = blockIdx.x * blockDim.x + threadIdx.x;
    if (i < n) g_dinv[i] = rsqrtf((float)g_deg[i] + 1.0f);
}

// ---------------- exclusive scan of deg -> rowptr ----------------
__global__ void scan1(int n) {
    __shared__ int sh[SCAN_BS];
    int tx = threadIdx.x;
    int i = blockIdx.x * SCAN_BS + tx;
    int v = (i < n) ? g_deg[i] : 0;
    sh[tx] = v;
    __syncthreads();
    for (int off = 1; off < SCAN_BS; off <<= 1) {
        int t = (tx >= off) ? sh[tx - off] : 0;
        __syncthreads();
        sh[tx] += t;
        __syncthreads();
    }
    int incl = sh[tx];
    if (i < n) g_rowptr[i] = incl - v;
    if (tx == SCAN_BS - 1) g_bsums[blockIdx.x] = incl;
}
__global__ void scan2(int nb, int e_total, int n) {
    int run = 0;
    for (int b = 0; b < nb; b++) { g_boff[b] = run; run += g_bsums[b]; }
    g_rowptr[n] = e_total;
}
__global__ void scan3(int n) {
    int i = blockIdx.x * blockDim.x + threadIdx.x;
    if (i >= n) return;
    int v = g_rowptr[i] + g_boff[i / SCAN_BS];
    g_rowptr[i] = v;
    g_wptr[i] = v;
}
__global__ void fill_csr(const int* __restrict__ ei, int e) {
    int idx = blockIdx.x * blockDim.x + threadIdx.x;
    if (idx >= e) return;
    int src = ei[idx];
    int dst = ei[e + idx];
    int pos = atomicAdd(&g_wptr[dst], 1);
    g_col[pos] = src;
    g_enorm[pos] = g_dinv[src] * g_dinv[dst];
}

// ---------------- tf32 mma.sync GEMM: [xa | xw] = x @ wcat^T ----------------
// block: 512 threads (16 warps, 4x4 warp grid), tile 128 rows x 256 cols, K=128
#define GT 512
#define LDP 132
#define GEMM_SMEM ((128 * LDP + 256 * LDP) * 4)

__device__ __forceinline__ uint32_t f2tf32(float f) {
    uint32_t u;
    asm("cvt.rna.tf32.f32 %0, %1;" : "=r"(u) : "f"(f));
    return u;
}

__global__ __launch_bounds__(GT, 1) void gemm_mma(const float* __restrict__ xin, int n) {
    extern __shared__ float sm[];
    float* As = sm;               // 128 x 132
    float* Bs = sm + 128 * LDP;   // 256 x 132

    int tid = threadIdx.x;
    int wid = tid >> 5;
    int lane = tid & 31;
    int rowBase = blockIdx.x << 7;

    // load B (weights), tf32-rounded
    for (int i = tid; i < 256 * 32; i += GT) {
        int j = i >> 5, c4 = i & 31;
        float4 v = ((const float4*)g_wcat)[i];
        float* dst = Bs + j * LDP + c4 * 4;
        dst[0] = __uint_as_float(f2tf32(v.x));
        dst[1] = __uint_as_float(f2tf32(v.y));
        dst[2] = __uint_as_float(f2tf32(v.z));
        dst[3] = __uint_as_float(f2tf32(v.w));
    }
    // load A tile (zero-pad OOB rows), tf32-rounded
    for (int i = tid; i < 128 * 32; i += GT) {
        int r = i >> 5, c4 = i & 31;
        int row = rowBase + r;
        float4 v = make_float4(0.f, 0.f, 0.f, 0.f);
        if (row < n) v = *(const float4*)(xin + row * D + c4 * 4);
        float* dst = As + r * LDP + c4 * 4;
        dst[0] = __uint_as_float(f2tf32(v.x));
        dst[1] = __uint_as_float(f2tf32(v.y));
        dst[2] = __uint_as_float(f2tf32(v.z));
        dst[3] = __uint_as_float(f2tf32(v.w));
    }
    __syncthreads();

    int wm = wid >> 2;
    int wn = wid & 3;
    int grp = lane >> 2;
    int tig = lane & 3;

    float c[2][8][4];
#pragma unroll
    for (int mt = 0; mt < 2; mt++)
#pragma unroll
        for (int nt = 0; nt < 8; nt++)
#pragma unroll
            for (int q = 0; q < 4; q++) c[mt][nt][q] = 0.f;

    const float* Abase = As + (wm * 32 + grp) * LDP + tig;
    const float* Bbase = Bs + (wn * 64 + grp) * LDP + tig;

#pragma unroll
    for (int ks = 0; ks < 16; ks++) {
        int k0 = ks * 8;
        uint32_t a[2][4], b[8][2];
#pragma unroll
        for (int mt = 0; mt < 2; mt++) {
            const float* ap = Abase + mt * 16 * LDP + k0;
            a[mt][0] = __float_as_uint(ap[0]);
            a[mt][1] = __float_as_uint(ap[8 * LDP]);
            a[mt][2] = __float_as_uint(ap[4]);
            a[mt][3] = __float_as_uint(ap[8 * LDP + 4]);
        }
#pragma unroll
        for (int nt = 0; nt < 8; nt++) {
            const float* bp = Bbase + nt * 8 * LDP + k0;
            b[nt][0] = __float_as_uint(bp[0]);
            b[nt][1] = __float_as_uint(bp[4]);
        }
#pragma unroll
        for (int mt = 0; mt < 2; mt++) {
#pragma unroll
            for (int nt = 0; nt < 8; nt++) {
                asm volatile(
                    "mma.sync.aligned.m16n8k8.row.col.f32.tf32.tf32.f32 "
                    "{%0,%1,%2,%3}, {%4,%5,%6,%7}, {%8,%9}, {%0,%1,%2,%3};"
                    : "+f"(c[mt][nt][0]), "+f"(c[mt][nt][1]),
                      "+f"(c[mt][nt][2]), "+f"(c[mt][nt][3])
                    : "r"(a[mt][0]), "r"(a[mt][1]), "r"(a[mt][2]), "r"(a[mt][3]),
                      "r"(b[nt][0]), "r"(b[nt][1]));
            }
        }
    }

    // epilogue: wn 0,1 -> xa (fp32) cols 0..127 ; wn 2,3 -> xwh (fp16) cols 0..127
    int colBase = (wn & 1) * 64 + 2 * tig;
    if (wn < 2) {
#pragma unroll
        for (int mt = 0; mt < 2; mt++) {
            int r0 = rowBase + wm * 32 + mt * 16 + grp;
            int r1 = r0 + 8;
#pragma unroll
            for (int nt = 0; nt < 8; nt++) {
                int col = colBase + nt * 8;
                if (r0 < n)
                    *(float2*)(g_xa + r0 * D + col) = make_float2(c[mt][nt][0], c[mt][nt][1]);
                if (r1 < n)
                    *(float2*)(g_xa + r1 * D + col) = make_float2(c[mt][nt][2], c[mt][nt][3]);
            }
        }
    } else {
#pragma unroll
        for (int mt = 0; mt < 2; mt++) {
            int r0 = rowBase + wm * 32 + mt * 16 + grp;
            int r1 = r0 + 8;
#pragma unroll
            for (int nt = 0; nt < 8; nt++) {
                int col = colBase + nt * 8;
                if (r0 < n)
                    *(__half2*)(g_xwh + r0 * D + col) =
                        __floats2half2_rn(c[mt][nt][0], c[mt][nt][1]);
                if (r1 < n)
                    *(__half2*)(g_xwh + r1 * D + col) =
                        __floats2half2_rn(c[mt][nt][2], c[mt][nt][3]);
            }
        }
    }
}

// ---------------- fused aggregate + update (fp16 gather) ----------------
// one warp per node; lane owns 4 cols (uint2 = 4 halfs)
__global__ __launch_bounds__(256) void agg_update(const float* __restrict__ xin,
                                                  float* __restrict__ xout,
                                                  const float* __restrict__ bias,
                                                  int n) {
    int gwarp = (blockIdx.x * blockDim.x + threadIdx.x) >> 5;
    int lane = threadIdx.x & 31;
    if (gwarp >= n) return;
    int i = gwarp;

    int start = g_rowptr[i];
    int end = g_rowptr[i + 1];

    const uint2* xwh = (const uint2*)g_xwh;   // row r: xwh[r*32 + lane] = cols lane*4..lane*4+3
    float4 acc = make_float4(0.f, 0.f, 0.f, 0.f);

    for (int j = start; j < end; j += 32) {
        int cnt = min(32, end - j);
        int c = 0;
        float w = 0.f;
        if (lane < cnt) {
            c = g_col[j + lane];
            w = g_enorm[j + lane];
        }
        int t = 0;
        for (; t + 4 <= cnt; t += 4) {
            int c0 = __shfl_sync(0xFFFFFFFFu, c, t + 0);
            int c1 = __shfl_sync(0xFFFFFFFFu, c, t + 1);
            int c2 = __shfl_sync(0xFFFFFFFFu, c, t + 2);
            int c3 = __shfl_sync(0xFFFFFFFFu, c, t + 3);
            float w0 = __shfl_sync(0xFFFFFFFFu, w, t + 0);
            float w1 = __shfl_sync(0xFFFFFFFFu, w, t + 1);
            float w2 = __shfl_sync(0xFFFFFFFFu, w, t + 2);
            float w3 = __shfl_sync(0xFFFFFFFFu, w, t + 3);
            uint2 u0 = __ldg(&xwh[c0 * 32 + lane]);
            uint2 u1 = __ldg(&xwh[c1 * 32 + lane]);
            uint2 u2 = __ldg(&xwh[c2 * 32 + lane]);
            uint2 u3 = __ldg(&xwh[c3 * 32 + lane]);
            {
                float2 p = __half22float2(*(__half2*)&u0.x);
                float2 q = __half22float2(*(__half2*)&u0.y);
                acc.x += w0 * p.x; acc.y += w0 * p.y; acc.z += w0 * q.x; acc.w += w0 * q.y;
            }
            {
                float2 p = __half22float2(*(__half2*)&u1.x);
                float2 q = __half22float2(*(__half2*)&u1.y);
                acc.x += w1 * p.x; acc.y += w1 * p.y; acc.z += w1 * q.x; acc.w += w1 * q.y;
            }
            {
                float2 p = __half22float2(*(__half2*)&u2.x);
                float2 q = __half22float2(*(__half2*)&u2.y);
                acc.x += w2 * p.x; acc.y += w2 * p.y; acc.z += w2 * q.x; acc.w += w2 * q.y;
            }
            {
                float2 p = __half22float2(*(__half2*)&u3.x);
                float2 q = __half22float2(*(__half2*)&u3.y);
                acc.x += w3 * p.x; acc.y += w3 * p.y; acc.z += w3 * q.x; acc.w += w3 * q.y;
            }
        }
        for (; t < cnt; t++) {
            int cc = __shfl_sync(0xFFFFFFFFu, c, t);
            float ww = __shfl_sync(0xFFFFFFFFu, w, t);
            uint2 u = __ldg(&xwh[cc * 32 + lane]);
            float2 p = __half22float2(*(__half2*)&u.x);
            float2 q = __half22float2(*(__half2*)&u.y);
            acc.x += ww * p.x; acc.y += ww * p.y; acc.z += ww * q.x; acc.w += ww * q.y;
        }
    }

    float dv = g_dinv[i];
    float d2 = dv * dv;

    float4 xa = __ldg(&((const float4*)g_xa)[i * 32 + lane]);
    uint2 us = __ldg(&xwh[i * 32 + lane]);
    float2 sp = __half22float2(*(__half2*)&us.x);
    float2 sq = __half22float2(*(__half2*)&us.y);
    float4 xv = __ldg(&((const float4*)xin)[i * 32 + lane]);
    float4 bv = __ldg(&((const float4*)bias)[lane]);

    float4 pre;
    pre.x = xa.x + acc.x + sp.x * d2 + bv.x;
    pre.y = xa.y + acc.y + sp.y * d2 + bv.y;
    pre.z = xa.z + acc.z + sq.x * d2 + bv.z;
    pre.w = xa.w + acc.w + sq.y * d2 + bv.w;

    float4 o;
    o.x = xv.x + EPS * tanhf(pre.x);
    o.y = xv.y + EPS * tanhf(pre.y);
    o.z = xv.z + EPS * tanhf(pre.z);
    o.w = xv.w + EPS * tanhf(pre.w);

    ((float4*)xout)[i * 32 + lane] = o;
}

// ---------------- launch ----------------
extern "C" void kernel_launch(void* const* d_in, const int* in_sizes, int n_in,
                              void* d_out, int out_size) {
    const float* x0   = (const float*)d_in[0];
    const int*   ei   = (const int*)d_in[1];
    const float* W    = (const float*)d_in[2];
    const float* Wphi = (const float*)d_in[3];
    const float* bias = (const float*)d_in[4];

    int n = in_sizes[0] / D;
    int e = in_sizes[1] / 2;
    if (n > MAXN) n = MAXN;
    if (e > MAXE) e = MAXE;

    float* xbuf = nullptr;
    cudaGetSymbolAddress((void**)&xbuf, g_xbuf);
    float* outp = (float*)d_out;

    cudaFuncSetAttribute(gemm_mma, cudaFuncAttributeMaxDynamicSharedMemorySize, GEMM_SMEM);

    // one-time graph preprocessing
    prep_weights<<<(256 * D + 255) / 256, 256>>>(W, Wphi);
    zero_deg<<<(n + 255) / 256, 256>>>(n);
    count_deg<<<(e + 255) / 256, 256>>>(ei, e);
    dinv_kernel<<<(n + 255) / 256, 256>>>(n);
    int nb = (n + SCAN_BS - 1) / SCAN_BS;
    scan1<<<nb, SCAN_BS>>>(n);
    scan2<<<1, 1>>>(nb, e, n);
    scan3<<<(n + 255) / 256, 256>>>(n);
    fill_csr<<<(e + 255) / 256, 256>>>(ei, e);

    // 4 iterations, ping-pong: x0 -> xbuf -> d_out -> xbuf -> d_out
    const float* xin = x0;
    int tiles = (n + 127) >> 7;
    for (int it = 0; it < 4; it++) {
        float* xout = (it % 2 == 0) ? xbuf : outp;
        gemm_mma<<<tiles, GT, GEMM_SMEM>>>(xin, n);
        agg_update<<<(n + 7) / 8, 256>>>(xin, xout, bias, n);
        xin = xout;
    }
}

// round 5
// speedup vs baseline: 2.0472x; 1.1392x over previous
#include <cuda_runtime.h>
#include <cuda_fp16.h>
#include <math.h>
#include <stdint.h>

#define D 128
#define GAMMA 0.1f
#define EPS 0.1f
#define MAXN 100000
#define MAXE 1600000
#define SCAN_BS 1024
#define MAXB ((MAXN + SCAN_BS - 1) / SCAN_BS)

// ---------------- scratch (static device globals; no allocation) ----------------
__device__ __align__(16) float  g_xa[MAXN * D];      // x @ A^T (fp32)
__device__ __align__(16) __half g_xwh[MAXN * D];     // x @ W_phi^T (fp16, for gather)
__device__ __align__(16) float  g_xbuf[MAXN * D];    // ping-pong x buffer
__device__ __align__(16) float  g_wcat[256 * D];     // row j<128: A row j; j>=128: Wphi row j-128
__device__ int   g_deg[MAXN];
__device__ float g_dinv[MAXN];
__device__ int   g_rowptr[MAXN + 1];
__device__ int   g_wptr[MAXN];
__device__ __align__(8) int2 g_edge[MAXE];           // .x = src col, .y = norm (float bits)
__device__ int   g_bsums[MAXB + 2];
__device__ int   g_boff[MAXB + 2];

// ---------------- prep: build concatenated weight (row-major [j][k]) ----------------
__global__ void prep_weights(const float* __restrict__ W, const float* __restrict__ Wphi) {
    int idx = blockIdx.x * blockDim.x + threadIdx.x;
    if (idx >= 256 * D) return;
    int j = idx / D;
    int k = idx % D;
    float v;
    if (j < D) {
        v = W[j * D + k] - W[k * D + j];
        if (j == k) v -= GAMMA;
    } else {
        v = Wphi[(j - D) * D + k];
    }
    g_wcat[j * D + k] = v;
}

// ---------------- degree / dinv ----------------
__global__ void zero_deg(int n) {
    int i = blockIdx.x * blockDim.x + threadIdx.x;
    if (i < n) g_deg[i] = 0;
}
__global__ void count_deg(const int* __restrict__ ei, int e) {
    int idx = blockIdx.x * blockDim.x + threadIdx.x;
    if (idx >= e) return;
    atomicAdd(&g_deg[ei[e + idx]], 1);
}
__global__ void dinv_kernel(int n) {
    int i = blockIdx.x * blockDim.x + threadIdx.x;
    if (i < n) g_dinv[i] = rsqrtf((float)g_deg[i] + 1.0f);
}

// ---------------- exclusive scan of deg -> rowptr ----------------
__global__ void scan1(int n) {
    __shared__ int sh[SCAN_BS];
    int tx = threadIdx.x;
    int i = blockIdx.x * SCAN_BS + tx;
    int v = (i < n) ? g_deg[i] : 0;
    sh[tx] = v;
    __syncthreads();
    for (int off = 1; off < SCAN_BS; off <<= 1) {
        int t = (tx >= off) ? sh[tx - off] : 0;
        __syncthreads();
        sh[tx] += t;
        __syncthreads();
    }
    int incl = sh[tx];
    if (i < n) g_rowptr[i] = incl - v;
    if (tx == SCAN_BS - 1) g_bsums[blockIdx.x] = incl;
}
__global__ void scan2(int nb, int e_total, int n) {
    int run = 0;
    for (int b = 0; b < nb; b++) { g_boff[b] = run; run += g_bsums[b]; }
    g_rowptr[n] = e_total;
}
__global__ void scan3(int n) {
    int i = blockIdx.x * blockDim.x + threadIdx.x;
    if (i >= n) return;
    int v = g_rowptr[i] + g_boff[i / SCAN_BS];
    g_rowptr[i] = v;
    g_wptr[i] = v;
}
__global__ void fill_csr(const int* __restrict__ ei, int e) {
    int idx = blockIdx.x * blockDim.x + threadIdx.x;
    if (idx >= e) return;
    int src = ei[idx];
    int dst = ei[e + idx];
    int pos = atomicAdd(&g_wptr[dst], 1);
    float nrm = g_dinv[src] * g_dinv[dst];
    g_edge[pos] = make_int2(src, __float_as_int(nrm));
}

// ---------------- tf32 mma.sync GEMM (persistent): [xa | xw] = x @ wcat^T ----------------
// grid = 148 persistent CTAs, 512 threads (16 warps, 4x4 warp grid)
// tile = 128 rows x 256 cols, K=128. B resident in SMEM for the whole kernel.
#define GT 512
#define LDP 132
#define GEMM_SMEM ((128 * LDP + 256 * LDP) * 4)

__device__ __forceinline__ uint32_t f2tf32(float f) {
    uint32_t u;
    asm("cvt.rna.tf32.f32 %0, %1;" : "=r"(u) : "f"(f));
    return u;
}

__global__ __launch_bounds__(GT, 1) void gemm_mma(const float* __restrict__ xin, int n, int tiles) {
    extern __shared__ float sm[];
    float* As = sm;               // 128 x 132
    float* Bs = sm + 128 * LDP;   // 256 x 132

    int tid = threadIdx.x;
    int wid = tid >> 5;
    int lane = tid & 31;

    // load B (weights) ONCE, tf32-rounded (RNA)
    for (int i = tid; i < 256 * 32; i += GT) {
        int j = i >> 5, c4 = i & 31;
        float4 v = ((const float4*)g_wcat)[i];
        float* dst = Bs + j * LDP + c4 * 4;
        dst[0] = __uint_as_float(f2tf32(v.x));
        dst[1] = __uint_as_float(f2tf32(v.y));
        dst[2] = __uint_as_float(f2tf32(v.z));
        dst[3] = __uint_as_float(f2tf32(v.w));
    }

    int wm = wid >> 2;
    int wn = wid & 3;
    int grp = lane >> 5 ? 0 : (lane >> 2);
    int tig = lane & 3;

    uint32_t As_base = (uint32_t)__cvta_generic_to_shared(As);

    const float* Abase = As + (wm * 32 + grp) * LDP + tig;
    const float* Bbase = Bs + (wn * 64 + grp) * LDP + tig;
    int colBase = (wn & 1) * 64 + 2 * tig;

    for (int t = blockIdx.x; t < tiles; t += gridDim.x) {
        int rowBase = t << 7;

        __syncthreads();   // As free (previous tile's MMA done)

        // async-load A tile: 128 rows x 128 cols fp32 (zero-fill OOB rows)
#pragma unroll
        for (int i = tid; i < 4096; i += GT) {
            int r = i >> 5, c4 = i & 31;
            int row = rowBase + r;
            uint32_t daddr = As_base + (uint32_t)(r * LDP + c4 * 4) * 4u;
            const float* src = xin + (size_t)row * D + c4 * 4;
            int sz = (row < n) ? 16 : 0;
            asm volatile("cp.async.ca.shared.global [%0], [%1], 16, %2;"
                         :: "r"(daddr), "l"(src), "r"(sz));
        }
        asm volatile("cp.async.commit_group;");
        asm volatile("cp.async.wait_group 0;");
        __syncthreads();

        float c[2][8][4];
#pragma unroll
        for (int mt = 0; mt < 2; mt++)
#pragma unroll
            for (int nt = 0; nt < 8; nt++)
#pragma unroll
                for (int q = 0; q < 4; q++) c[mt][nt][q] = 0.f;

#pragma unroll
        for (int ks = 0; ks < 16; ks++) {
            int k0 = ks * 8;
            uint32_t a[2][4], b[8][2];
#pragma unroll
            for (int mt = 0; mt < 2; mt++) {
                const float* ap = Abase + mt * 16 * LDP + k0;
                a[mt][0] = __float_as_uint(ap[0]);
                a[mt][1] = __float_as_uint(ap[8 * LDP]);
                a[mt][2] = __float_as_uint(ap[4]);
                a[mt][3] = __float_as_uint(ap[8 * LDP + 4]);
            }
#pragma unroll
            for (int nt = 0; nt < 8; nt++) {
                const float* bp = Bbase + nt * 8 * LDP + k0;
                b[nt][0] = __float_as_uint(bp[0]);
                b[nt][1] = __float_as_uint(bp[4]);
            }
#pragma unroll
            for (int mt = 0; mt < 2; mt++) {
#pragma unroll
                for (int nt = 0; nt < 8; nt++) {
                    asm volatile(
                        "mma.sync.aligned.m16n8k8.row.col.f32.tf32.tf32.f32 "
                        "{%0,%1,%2,%3}, {%4,%5,%6,%7}, {%8,%9}, {%0,%1,%2,%3};"
                        : "+f"(c[mt][nt][0]), "+f"(c[mt][nt][1]),
                          "+f"(c[mt][nt][2]), "+f"(c[mt][nt][3])
                        : "r"(a[mt][0]), "r"(a[mt][1]), "r"(a[mt][2]), "r"(a[mt][3]),
                          "r"(b[nt][0]), "r"(b[nt][1]));
                }
            }
        }

        // epilogue: wn 0,1 -> xa (fp32); wn 2,3 -> xwh (fp16)
        if (wn < 2) {
#pragma unroll
            for (int mt = 0; mt < 2; mt++) {
                int r0 = rowBase + wm * 32 + mt * 16 + grp;
                int r1 = r0 + 8;
#pragma unroll
                for (int nt = 0; nt < 8; nt++) {
                    int col = colBase + nt * 8;
                    if (r0 < n)
                        *(float2*)(g_xa + (size_t)r0 * D + col) = make_float2(c[mt][nt][0], c[mt][nt][1]);
                    if (r1 < n)
                        *(float2*)(g_xa + (size_t)r1 * D + col) = make_float2(c[mt][nt][2], c[mt][nt][3]);
                }
            }
        } else {
#pragma unroll
            for (int mt = 0; mt < 2; mt++) {
                int r0 = rowBase + wm * 32 + mt * 16 + grp;
                int r1 = r0 + 8;
#pragma unroll
                for (int nt = 0; nt < 8; nt++) {
                    int col = colBase + nt * 8;
                    if (r0 < n)
                        *(__half2*)(g_xwh + (size_t)r0 * D + col) =
                            __floats2half2_rn(c[mt][nt][0], c[mt][nt][1]);
                    if (r1 < n)
                        *(__half2*)(g_xwh + (size_t)r1 * D + col) =
                            __floats2half2_rn(c[mt][nt][2], c[mt][nt][3]);
                }
            }
        }
    }
}

// ---------------- fused aggregate + update (paired fp16 gather) ----------------
// one warp per node; 16 lanes cover a 256B row (uint4 each); 2 edges per LDG.128
__global__ __launch_bounds__(256) void agg_update(const float* __restrict__ xin,
                                                  float* __restrict__ xout,
                                                  const float* __restrict__ bias,
                                                  int n) {
    int node = (blockIdx.x * blockDim.x + threadIdx.x) >> 5;
    int lane = threadIdx.x & 31;
    if (node >= n) return;

    int start = g_rowptr[node];
    int end = g_rowptr[node + 1];

    int sub = lane & 15;     // 16B chunk within row
    int hi = lane >> 4;      // 0: even edge, 1: odd edge

    const uint4* xwq = (const uint4*)g_xwh;   // row r: xwq[r*16 + sub] = halfs sub*8..sub*8+7

    float acc[8];
#pragma unroll
    for (int q = 0; q < 8; q++) acc[q] = 0.f;

    for (int j = start; j < end; j += 32) {
        int cnt = min(32, end - j);
        int c = 0;
        float w = 0.f;
        if (lane < cnt) {
            int2 eb = __ldg(&g_edge[j + lane]);
            c = eb.x;
            w = __int_as_float(eb.y);
        }
        int t = 0;
        // 4 pairs (8 edges) per unrolled step -> 4 independent LDG.128
        for (; t + 8 <= cnt; t += 8) {
            int myc[4];
            float myw[4];
#pragma unroll
            for (int p = 0; p < 4; p++) {
                int cl = __shfl_sync(0xFFFFFFFFu, c, t + 2 * p);
                int ch = __shfl_sync(0xFFFFFFFFu, c, t + 2 * p + 1);
                float wl = __shfl_sync(0xFFFFFFFFu, w, t + 2 * p);
                float wh = __shfl_sync(0xFFFFFFFFu, w, t + 2 * p + 1);
                myc[p] = hi ? ch : cl;
                myw[p] = hi ? wh : wl;
            }
            uint4 u[4];
#pragma unroll
            for (int p = 0; p < 4; p++) u[p] = __ldg(&xwq[(size_t)myc[p] * 16 + sub]);
#pragma unroll
            for (int p = 0; p < 4; p++) {
                float2 f0 = __half22float2(*(__half2*)&u[p].x);
                float2 f1 = __half22float2(*(__half2*)&u[p].y);
                float2 f2 = __half22float2(*(__half2*)&u[p].z);
                float2 f3 = __half22float2(*(__half2*)&u[p].w);
                acc[0] += myw[p] * f0.x; acc[1] += myw[p] * f0.y;
                acc[2] += myw[p] * f1.x; acc[3] += myw[p] * f1.y;
                acc[4] += myw[p] * f2.x; acc[5] += myw[p] * f2.y;
                acc[6] += myw[p] * f3.x; acc[7] += myw[p] * f3.y;
            }
        }
        // remainder pairs
        for (; t < cnt; t += 2) {
            int cl = __shfl_sync(0xFFFFFFFFu, c, t);
            float wl = __shfl_sync(0xFFFFFFFFu, w, t);
            int ch = cl;
            float wh = 0.f;
            if (t + 1 < cnt) {
                ch = __shfl_sync(0xFFFFFFFFu, c, t + 1);
                wh = __shfl_sync(0xFFFFFFFFu, w, t + 1);
            }
            int myc = hi ? ch : cl;
            float myw = hi ? wh : wl;
            uint4 u = __ldg(&xwq[(size_t)myc * 16 + sub]);
            float2 f0 = __half22float2(*(__half2*)&u.x);
            float2 f1 = __half22float2(*(__half2*)&u.y);
            float2 f2 = __half22float2(*(__half2*)&u.z);
            float2 f3 = __half22float2(*(__half2*)&u.w);
            acc[0] += myw * f0.x; acc[1] += myw * f0.y;
            acc[2] += myw * f1.x; acc[3] += myw * f1.y;
            acc[4] += myw * f2.x; acc[5] += myw * f2.y;
            acc[6] += myw * f3.x; acc[7] += myw * f3.y;
        }
    }

    // combine even/odd-edge partials
#pragma unroll
    for (int q = 0; q < 8; q++) acc[q] += __shfl_xor_sync(0xFFFFFFFFu, acc[q], 16);

    // epilogue: lanes 0..15 own 8 cols each (cols sub*8 .. sub*8+7)
    if (hi == 0) {
        float dv = g_dinv[node];
        float d2 = dv * dv;

        uint4 us = __ldg(&xwq[(size_t)node * 16 + sub]);
        float2 s0 = __half22float2(*(__half2*)&us.x);
        float2 s1 = __half22float2(*(__half2*)&us.y);
        float2 s2 = __half22float2(*(__half2*)&us.z);
        float2 s3 = __half22float2(*(__half2*)&us.w);
        float self[8] = {s0.x, s0.y, s1.x, s1.y, s2.x, s2.y, s3.x, s3.y};

        const float4* xa4 = (const float4*)(g_xa + (size_t)node * D) + sub * 2;
        const float4* xv4 = (const float4*)(xin + (size_t)node * D) + sub * 2;
        const float4* bv4 = (const float4*)bias + sub * 2;
        float4* out4 = (float4*)(xout + (size_t)node * D) + sub * 2;

#pragma unroll
        for (int h = 0; h < 2; h++) {
            float4 xa = __ldg(&xa4[h]);
            float4 xv = __ldg(&xv4[h]);
            float4 bv = __ldg(&bv4[h]);
            float4 o;
            o.x = xv.x + EPS * tanhf(xa.x + acc[h * 4 + 0] + self[h * 4 + 0] * d2 + bv.x);
            o.y = xv.y + EPS * tanhf(xa.y + acc[h * 4 + 1] + self[h * 4 + 1] * d2 + bv.y);
            o.z = xv.z + EPS * tanhf(xa.z + acc[h * 4 + 2] + self[h * 4 + 2] * d2 + bv.z);
            o.w = xv.w + EPS * tanhf(xa.w + acc[h * 4 + 3] + self[h * 4 + 3] * d2 + bv.w);
            out4[h] = o;
        }
    }
}

// ---------------- launch ----------------
extern "C" void kernel_launch(void* const* d_in, const int* in_sizes, int n_in,
                              void* d_out, int out_size) {
    const float* x0   = (const float*)d_in[0];
    const int*   ei   = (const int*)d_in[1];
    const float* W    = (const float*)d_in[2];
    const float* Wphi = (const float*)d_in[3];
    const float* bias = (const float*)d_in[4];

    int n = in_sizes[0] / D;
    int e = in_sizes[1] / 2;
    if (n > MAXN) n = MAXN;
    if (e > MAXE) e = MAXE;

    float* xbuf = nullptr;
    cudaGetSymbolAddress((void**)&xbuf, g_xbuf);
    float* outp = (float*)d_out;

    cudaFuncSetAttribute(gemm_mma, cudaFuncAttributeMaxDynamicSharedMemorySize, GEMM_SMEM);

    // one-time graph preprocessing
    prep_weights<<<(256 * D + 255) / 256, 256>>>(W, Wphi);
    zero_deg<<<(n + 255) / 256, 256>>>(n);
    count_deg<<<(e + 255) / 256, 256>>>(ei, e);
    dinv_kernel<<<(n + 255) / 256, 256>>>(n);
    int nb = (n + SCAN_BS - 1) / SCAN_BS;
    scan1<<<nb, SCAN_BS>>>(n);
    scan2<<<1, 1>>>(nb, e, n);
    scan3<<<(n + 255) / 256, 256>>>(n);
    fill_csr<<<(e + 255) / 256, 256>>>(ei, e);

    // 4 iterations, ping-pong: x0 -> xbuf -> d_out -> xbuf -> d_out
    const float* xin = x0;
    int tiles = (n + 127) >> 7;
    for (int it = 0; it < 4; it++) {
        float* xout = (it % 2 == 0) ? xbuf : outp;
        gemm_mma<<<148, GT, GEMM_SMEM>>>(xin, n, tiles);
        agg_update<<<(n + 7) / 8, 256>>>(xin, xout, bias, n);
        xin = xout;
    }
}

// round 6
// speedup vs baseline: 2.1262x; 1.0386x over previous
#include <cuda_runtime.h>
#include <cuda_fp16.h>
#include <math.h>
#include <stdint.h>

#define D 128
#define GAMMA 0.1f
#define EPS 0.1f
#define MAXN 100000
#define MAXE 1600000
#define SCAN_BS 1024
#define MAXB ((MAXN + SCAN_BS - 1) / SCAN_BS)

// ---------------- scratch (static device globals; no allocation) ----------------
__device__ __align__(16) __half g_xh[MAXN * 256];    // row: [xa (128) | xw (128)] fp16
__device__ __align__(16) float  g_xbuf[MAXN * D];    // ping-pong x buffer
__device__ __align__(16) float  g_wcat[256 * D];     // row j<128: A row j; j>=128: Wphi row j-128
__device__ int   g_deg[MAXN];
__device__ float g_dinv[MAXN];
__device__ int   g_rowptr[MAXN + 1];
__device__ int   g_wptr[MAXN];
__device__ __align__(8) int2 g_edge[MAXE];           // .x = src col, .y = norm (float bits)
__device__ int   g_bsums[MAXB + 2];
__device__ int   g_boff[MAXB + 2];

__device__ __forceinline__ float tanh_fast(float x) {
    float r;
    asm("tanh.approx.f32 %0, %1;" : "=f"(r) : "f"(x));
    return r;
}

// ---------------- prep: build concatenated weight (row-major [j][k]) ----------------
__global__ void prep_weights(const float* __restrict__ W, const float* __restrict__ Wphi) {
    int idx = blockIdx.x * blockDim.x + threadIdx.x;
    if (idx >= 256 * D) return;
    int j = idx / D;
    int k = idx % D;
    float v;
    if (j < D) {
        v = W[j * D + k] - W[k * D + j];
        if (j == k) v -= GAMMA;
    } else {
        v = Wphi[(j - D) * D + k];
    }
    g_wcat[j * D + k] = v;
}

// ---------------- degree / dinv ----------------
__global__ void zero_deg(int n) {
    int i = blockIdx.x * blockDim.x + threadIdx.x;
    if (i < n) g_deg[i] = 0;
}
__global__ void count_deg(const int* __restrict__ ei, int e) {
    int idx = blockIdx.x * blockDim.x + threadIdx.x;
    if (idx >= e) return;
    atomicAdd(&g_deg[ei[e + idx]], 1);
}
__global__ void dinv_kernel(int n) {
    int i = blockIdx.x * blockDim.x + threadIdx.x;
    if (i < n) g_dinv[i] = rsqrtf((float)g_deg[i] + 1.0f);
}

// ---------------- exclusive scan of deg -> rowptr ----------------
__global__ void scan1(int n) {
    __shared__ int sh[SCAN_BS];
    int tx = threadIdx.x;
    int i = blockIdx.x * SCAN_BS + tx;
    int v = (i < n) ? g_deg[i] : 0;
    sh[tx] = v;
    __syncthreads();
    for (int off = 1; off < SCAN_BS; off <<= 1) {
        int t = (tx >= off) ? sh[tx - off] : 0;
        __syncthreads();
        sh[tx] += t;
        __syncthreads();
    }
    int incl = sh[tx];
    if (i < n) g_rowptr[i] = incl - v;
    if (tx == SCAN_BS - 1) g_bsums[blockIdx.x] = incl;
}
__global__ void scan2(int nb, int e_total, int n) {
    int run = 0;
    for (int b = 0; b < nb; b++) { g_boff[b] = run; run += g_bsums[b]; }
    g_rowptr[n] = e_total;
}
__global__ void scan3(int n) {
    int i = blockIdx.x * blockDim.x + threadIdx.x;
    if (i >= n) return;
    int v = g_rowptr[i] + g_boff[i / SCAN_BS];
    g_rowptr[i] = v;
    g_wptr[i] = v;
}
__global__ void fill_csr(const int* __restrict__ ei, int e) {
    int idx = blockIdx.x * blockDim.x + threadIdx.x;
    if (idx >= e) return;
    int src = ei[idx];
    int dst = ei[e + idx];
    int pos = atomicAdd(&g_wptr[dst], 1);
    float nrm = g_dinv[src] * g_dinv[dst];
    g_edge[pos] = make_int2(src, __float_as_int(nrm));
}

// ---------------- tf32 mma.sync GEMM (persistent): [xa | xw] = x @ wcat^T ----------------
// grid = 148 persistent CTAs, 512 threads (16 warps, 4x4 warp grid)
// tile = 128 rows x 256 cols, K=128. B resident in SMEM for the whole kernel.
#define GT 512
#define LDP 132
#define GEMM_SMEM ((128 * LDP + 256 * LDP) * 4)

__device__ __forceinline__ uint32_t f2tf32(float f) {
    uint32_t u;
    asm("cvt.rna.tf32.f32 %0, %1;" : "=r"(u) : "f"(f));
    return u;
}

__global__ __launch_bounds__(GT, 1) void gemm_mma(const float* __restrict__ xin, int n, int tiles) {
    extern __shared__ float sm[];
    float* As = sm;               // 128 x 132
    float* Bs = sm + 128 * LDP;   // 256 x 132

    int tid = threadIdx.x;
    int wid = tid >> 5;
    int lane = tid & 31;

    // load B (weights) ONCE, tf32-rounded (RNA)
    for (int i = tid; i < 256 * 32; i += GT) {
        int j = i >> 5, c4 = i & 31;
        float4 v = ((const float4*)g_wcat)[i];
        float* dst = Bs + j * LDP + c4 * 4;
        dst[0] = __uint_as_float(f2tf32(v.x));
        dst[1] = __uint_as_float(f2tf32(v.y));
        dst[2] = __uint_as_float(f2tf32(v.z));
        dst[3] = __uint_as_float(f2tf32(v.w));
    }

    int wm = wid >> 2;
    int wn = wid & 3;
    int grp = lane >> 2;
    int tig = lane & 3;

    uint32_t As_base = (uint32_t)__cvta_generic_to_shared(As);

    const float* Abase = As + (wm * 32 + grp) * LDP + tig;
    const float* Bbase = Bs + (wn * 64 + grp) * LDP + tig;
    // global column in the 256-wide [xa | xw] row
    int gcolBase = (wn >= 2 ? 128 : 0) + (wn & 1) * 64 + 2 * tig;

    for (int t = blockIdx.x; t < tiles; t += gridDim.x) {
        int rowBase = t << 7;

        __syncthreads();   // As free (previous tile's MMA done)

        // async-load A tile: 128 rows x 128 cols fp32 (zero-fill OOB rows)
#pragma unroll
        for (int i = tid; i < 4096; i += GT) {
            int r = i >> 5, c4 = i & 31;
            int row = rowBase + r;
            uint32_t daddr = As_base + (uint32_t)(r * LDP + c4 * 4) * 4u;
            const float* src = xin + (size_t)row * D + c4 * 4;
            int sz = (row < n) ? 16 : 0;
            asm volatile("cp.async.ca.shared.global [%0], [%1], 16, %2;"
                         :: "r"(daddr), "l"(src), "r"(sz));
        }
        asm volatile("cp.async.commit_group;");
        asm volatile("cp.async.wait_group 0;");
        __syncthreads();

        float c[2][8][4];
#pragma unroll
        for (int mt = 0; mt < 2; mt++)
#pragma unroll
            for (int nt = 0; nt < 8; nt++)
#pragma unroll
                for (int q = 0; q < 4; q++) c[mt][nt][q] = 0.f;

#pragma unroll
        for (int ks = 0; ks < 16; ks++) {
            int k0 = ks * 8;
            uint32_t a[2][4], b[8][2];
#pragma unroll
            for (int mt = 0; mt < 2; mt++) {
                const float* ap = Abase + mt * 16 * LDP + k0;
                a[mt][0] = __float_as_uint(ap[0]);
                a[mt][1] = __float_as_uint(ap[8 * LDP]);
                a[mt][2] = __float_as_uint(ap[4]);
                a[mt][3] = __float_as_uint(ap[8 * LDP + 4]);
            }
#pragma unroll
            for (int nt = 0; nt < 8; nt++) {
                const float* bp = Bbase + nt * 8 * LDP + k0;
                b[nt][0] = __float_as_uint(bp[0]);
                b[nt][1] = __float_as_uint(bp[4]);
            }
#pragma unroll
            for (int mt = 0; mt < 2; mt++) {
#pragma unroll
                for (int nt = 0; nt < 8; nt++) {
                    asm volatile(
                        "mma.sync.aligned.m16n8k8.row.col.f32.tf32.tf32.f32 "
                        "{%0,%1,%2,%3}, {%4,%5,%6,%7}, {%8,%9}, {%0,%1,%2,%3};"
                        : "+f"(c[mt][nt][0]), "+f"(c[mt][nt][1]),
                          "+f"(c[mt][nt][2]), "+f"(c[mt][nt][3])
                        : "r"(a[mt][0]), "r"(a[mt][1]), "r"(a[mt][2]), "r"(a[mt][3]),
                          "r"(b[nt][0]), "r"(b[nt][1]));
                }
            }
        }

        // epilogue: all warps write fp16 into the combined [xa | xw] row
#pragma unroll
        for (int mt = 0; mt < 2; mt++) {
            int r0 = rowBase + wm * 32 + mt * 16 + grp;
            int r1 = r0 + 8;
#pragma unroll
            for (int nt = 0; nt < 8; nt++) {
                int gcol = gcolBase + nt * 8;
                if (r0 < n)
                    *(__half2*)(g_xh + (size_t)r0 * 256 + gcol) =
                        __floats2half2_rn(c[mt][nt][0], c[mt][nt][1]);
                if (r1 < n)
                    *(__half2*)(g_xh + (size_t)r1 * 256 + gcol) =
                        __floats2half2_rn(c[mt][nt][2], c[mt][nt][3]);
            }
        }
    }
}

// ---------------- fused aggregate + update (paired fp16 gather) ----------------
// one warp per node; 16 lanes cover a 256B xw half-row (uint4 each); 2 edges per LDG.128
__global__ __launch_bounds__(256) void agg_update(const float* __restrict__ xin,
                                                  float* __restrict__ xout,
                                                  const float* __restrict__ bias,
                                                  int n) {
    int node = (blockIdx.x * blockDim.x + threadIdx.x) >> 5;
    int lane = threadIdx.x & 31;
    if (node >= n) return;

    int start = g_rowptr[node];
    int end = g_rowptr[node + 1];

    int sub = lane & 15;     // 16B chunk within xw half-row
    int hi = lane >> 4;      // 0: even edge, 1: odd edge

    // g_xh row r as uint4[32]: [0..15] = xa half, [16..31] = xw half
    const uint4* xq = (const uint4*)g_xh;

    float acc[8];
#pragma unroll
    for (int q = 0; q < 8; q++) acc[q] = 0.f;

    for (int j = start; j < end; j += 32) {
        int cnt = min(32, end - j);
        int c = 0;
        float w = 0.f;
        if (lane < cnt) {
            int2 eb = __ldg(&g_edge[j + lane]);
            c = eb.x;
            w = __int_as_float(eb.y);
        }
        int t = 0;
        // 4 pairs (8 edges) per unrolled step -> 4 independent LDG.128
        for (; t + 8 <= cnt; t += 8) {
            int myc[4];
            float myw[4];
#pragma unroll
            for (int p = 0; p < 4; p++) {
                int cl = __shfl_sync(0xFFFFFFFFu, c, t + 2 * p);
                int ch = __shfl_sync(0xFFFFFFFFu, c, t + 2 * p + 1);
                float wl = __shfl_sync(0xFFFFFFFFu, w, t + 2 * p);
                float wh = __shfl_sync(0xFFFFFFFFu, w, t + 2 * p + 1);
                myc[p] = hi ? ch : cl;
                myw[p] = hi ? wh : wl;
            }
            uint4 u[4];
#pragma unroll
            for (int p = 0; p < 4; p++)
                u[p] = __ldg(&xq[(size_t)myc[p] * 32 + 16 + sub]);
#pragma unroll
            for (int p = 0; p < 4; p++) {
                float2 f0 = __half22float2(*(__half2*)&u[p].x);
                float2 f1 = __half22float2(*(__half2*)&u[p].y);
                float2 f2 = __half22float2(*(__half2*)&u[p].z);
                float2 f3 = __half22float2(*(__half2*)&u[p].w);
                acc[0] += myw[p] * f0.x; acc[1] += myw[p] * f0.y;
                acc[2] += myw[p] * f1.x; acc[3] += myw[p] * f1.y;
                acc[4] += myw[p] * f2.x; acc[5] += myw[p] * f2.y;
                acc[6] += myw[p] * f3.x; acc[7] += myw[p] * f3.y;
            }
        }
        // remainder pairs
        for (; t < cnt; t += 2) {
            int cl = __shfl_sync(0xFFFFFFFFu, c, t);
            float wl = __shfl_sync(0xFFFFFFFFu, w, t);
            int ch = cl;
            float wh = 0.f;
            if (t + 1 < cnt) {
                ch = __shfl_sync(0xFFFFFFFFu, c, t + 1);
                wh = __shfl_sync(0xFFFFFFFFu, w, t + 1);
            }
            int myc = hi ? ch : cl;
            float myw = hi ? wh : wl;
            uint4 u = __ldg(&xq[(size_t)myc * 32 + 16 + sub]);
            float2 f0 = __half22float2(*(__half2*)&u.x);
            float2 f1 = __half22float2(*(__half2*)&u.y);
            float2 f2 = __half22float2(*(__half2*)&u.z);
            float2 f3 = __half22float2(*(__half2*)&u.w);
            acc[0] += myw * f0.x; acc[1] += myw * f0.y;
            acc[2] += myw * f1.x; acc[3] += myw * f1.y;
            acc[4] += myw * f2.x; acc[5] += myw * f2.y;
            acc[6] += myw * f3.x; acc[7] += myw * f3.y;
        }
    }

    // combine even/odd-edge partials
#pragma unroll
    for (int q = 0; q < 8; q++) acc[q] += __shfl_xor_sync(0xFFFFFFFFu, acc[q], 16);

    // epilogue: lanes 0..15 own 8 cols each (cols sub*8 .. sub*8+7)
    if (hi == 0) {
        float dv = g_dinv[node];
        float d2 = dv * dv;

        uint4 ua = __ldg(&xq[(size_t)node * 32 + sub]);        // xa (fp16)
        uint4 us = __ldg(&xq[(size_t)node * 32 + 16 + sub]);   // xw self (fp16)
        float2 a0 = __half22float2(*(__half2*)&ua.x);
        float2 a1 = __half22float2(*(__half2*)&ua.y);
        float2 a2 = __half22float2(*(__half2*)&ua.z);
        float2 a3 = __half22float2(*(__half2*)&ua.w);
        float2 s0 = __half22float2(*(__half2*)&us.x);
        float2 s1 = __half22float2(*(__half2*)&us.y);
        float2 s2 = __half22float2(*(__half2*)&us.z);
        float2 s3 = __half22float2(*(__half2*)&us.w);
        float xa[8] = {a0.x, a0.y, a1.x, a1.y, a2.x, a2.y, a3.x, a3.y};
        float self[8] = {s0.x, s0.y, s1.x, s1.y, s2.x, s2.y, s3.x, s3.y};

        const float4* xv4 = (const float4*)(xin + (size_t)node * D) + sub * 2;
        const float4* bv4 = (const float4*)bias + sub * 2;
        float4* out4 = (float4*)(xout + (size_t)node * D) + sub * 2;

#pragma unroll
        for (int h = 0; h < 2; h++) {
            float4 xv = __ldg(&xv4[h]);
            float4 bv = __ldg(&bv4[h]);
            float4 o;
            o.x = xv.x + EPS * tanh_fast(xa[h * 4 + 0] + acc[h * 4 + 0] + self[h * 4 + 0] * d2 + bv.x);
            o.y = xv.y + EPS * tanh_fast(xa[h * 4 + 1] + acc[h * 4 + 1] + self[h * 4 + 1] * d2 + bv.y);
            o.z = xv.z + EPS * tanh_fast(xa[h * 4 + 2] + acc[h * 4 + 2] + self[h * 4 + 2] * d2 + bv.z);
            o.w = xv.w + EPS * tanh_fast(xa[h * 4 + 3] + acc[h * 4 + 3] + self[h * 4 + 3] * d2 + bv.w);
            out4[h] = o;
        }
    }
}

// ---------------- launch ----------------
extern "C" void kernel_launch(void* const* d_in, const int* in_sizes, int n_in,
                              void* d_out, int out_size) {
    const float* x0   = (const float*)d_in[0];
    const int*   ei   = (const int*)d_in[1];
    const float* W    = (const float*)d_in[2];
    const float* Wphi = (const float*)d_in[3];
    const float* bias = (const float*)d_in[4];

    int n = in_sizes[0] / D;
    int e = in_sizes[1] / 2;
    if (n > MAXN) n = MAXN;
    if (e > MAXE) e = MAXE;

    float* xbuf = nullptr;
    cudaGetSymbolAddress((void**)&xbuf, g_xbuf);
    float* outp = (float*)d_out;

    cudaFuncSetAttribute(gemm_mma, cudaFuncAttributeMaxDynamicSharedMemorySize, GEMM_SMEM);

    // one-time graph preprocessing
    prep_weights<<<(256 * D + 255) / 256, 256>>>(W, Wphi);
    zero_deg<<<(n + 255) / 256, 256>>>(n);
    count_deg<<<(e + 255) / 256, 256>>>(ei, e);
    dinv_kernel<<<(n + 255) / 256, 256>>>(n);
    int nb = (n + SCAN_BS - 1) / SCAN_BS;
    scan1<<<nb, SCAN_BS>>>(n);
    scan2<<<1, 1>>>(nb, e, n);
    scan3<<<(n + 255) / 256, 256>>>(n);
    fill_csr<<<(e + 255) / 256, 256>>>(ei, e);

    // 4 iterations, ping-pong: x0 -> xbuf -> d_out -> xbuf -> d_out
    const float* xin = x0;
    int tiles = (n + 127) >> 7;
    for (int it = 0; it < 4; it++) {
        float* xout = (it % 2 == 0) ? xbuf : outp;
        gemm_mma<<<148, GT, GEMM_SMEM>>>(xin, n, tiles);
        agg_update<<<(n + 7) / 8, 256>>>(xin, xout, bias, n);
        xin = xout;
    }
}